// round 3
// baseline (speedup 1.0000x reference)
#include <cuda_runtime.h>
#include <cuda_bf16.h>

// GCN 2-layer: x[500000,3], edge_index[2,4000000] (int32), W1[3,16], b1[16],
// W2[16,1], b2[1] -> out[500000,1] float32.
//
// PyG GCNConv: add self-loops, deg on target (col) side, norm=dinv[r]*dinv[c],
// scatter-add to col, bias; ReLU between layers.
//
// Key algebraic restructure: target-side dinv[c] factored out of the edge sum
// and applied in the node epilogue, so edge kernels never touch dinv[c].
// Source side packed as g_xp[n] = {x0,x1,x2,dinv} -> single 16B (1-sector)
// random gather per edge; msg = (dinv_r * x_r) @ W1 computed in registers.

constexpr int NN = 500000;
constexpr int NE = 4000000;
constexpr int F  = 16;

// Scratch (device globals: allocation-free per harness rules)
__device__ float4 g_xp[NN];               // {x0,x1,x2,dinv} packed per node
__device__ float  g_agg1[(size_t)NN * F]; // layer-1 edge agg (unscaled by dinv_c)
__device__ float  g_dinv[NN];             // deg^{-1/2}
__device__ float  g_z[NN];                // layer-2 linear output per node
__device__ float  g_zn[NN];               // z[n] * dinv[n] (pre-scaled for gather)
__device__ float  g_agg2[NN];             // layer-2 edge agg (unscaled by dinv_c)
__device__ int    g_deg[NN];              // incoming-edge count

// ---------------------------------------------------------------------------
__global__ void k_zero() {
    int tid = blockIdx.x * blockDim.x + threadIdx.x;
    int stride = gridDim.x * blockDim.x;
    float4* a1 = reinterpret_cast<float4*>(g_agg1);
    for (int j = tid; j < NN * F / 4; j += stride)
        a1[j] = make_float4(0.f, 0.f, 0.f, 0.f);
    for (int j = tid; j < NN; j += stride) { g_agg2[j] = 0.0f; g_deg[j] = 0; }
}

// Degree of target nodes. 4 edges per thread via int4 load. g_deg is 2MB,
// fully L2-resident -> atomics are cheap.
__global__ void k_deg(const int* __restrict__ col) {
    int i = blockIdx.x * blockDim.x + threadIdx.x;
    int e = i * 4;
    if (e + 3 < NE) {
        int4 c4 = *reinterpret_cast<const int4*>(col + e);
        atomicAdd(&g_deg[c4.x], 1);
        atomicAdd(&g_deg[c4.y], 1);
        atomicAdd(&g_deg[c4.z], 1);
        atomicAdd(&g_deg[c4.w], 1);
    } else {
        for (; e < NE; ++e) atomicAdd(&g_deg[col[e]], 1);
    }
}

// Pack {x, dinv} per node.
__global__ void k_prep(const float* __restrict__ x) {
    int n = blockIdx.x * blockDim.x + threadIdx.x;
    if (n >= NN) return;
    float d = rsqrtf((float)(g_deg[n] + 1));  // + self-loop
    g_dinv[n] = d;
    float4 p;
    p.x = x[(size_t)n * 3 + 0];
    p.y = x[(size_t)n * 3 + 1];
    p.z = x[(size_t)n * 3 + 2];
    p.w = d;
    g_xp[n] = p;
}

// Dominant kernel: grid-stride, 4 edges per iteration. W1 register-resident.
// Per edge: 16B gather of {x,dinv}, 51 FMA, 4x red.global.add.v4.f32.
__global__ void k_edge1(const int* __restrict__ row, const int* __restrict__ col,
                        const float* __restrict__ W1) {
    float W[48];
#pragma unroll
    for (int j = 0; j < 48; ++j) W[j] = __ldg(W1 + j);

    int nq = NE / 4;  // NE divisible by 4
    int stride = gridDim.x * blockDim.x;
    for (int q = blockIdx.x * blockDim.x + threadIdx.x; q < nq; q += stride) {
        int e = q * 4;
        int4 r4 = *reinterpret_cast<const int4*>(row + e);
        int4 c4 = *reinterpret_cast<const int4*>(col + e);
        // Front-batch the 4 independent gathers (MLP=4 within thread).
        float4 p0 = __ldg(&g_xp[r4.x]);
        float4 p1 = __ldg(&g_xp[r4.y]);
        float4 p2 = __ldg(&g_xp[r4.z]);
        float4 p3 = __ldg(&g_xp[r4.w]);
        const float4* ps[4] = {&p0, &p1, &p2, &p3};
        int cs[4] = {c4.x, c4.y, c4.z, c4.w};
#pragma unroll
        for (int u = 0; u < 4; ++u) {
            float4 p = *ps[u];
            float s0 = p.x * p.w, s1 = p.y * p.w, s2 = p.z * p.w;
            float* op = g_agg1 + (size_t)cs[u] * F;
#pragma unroll
            for (int qq = 0; qq < 4; ++qq) {
                float m0 = s0 * W[qq * 4 + 0] + s1 * W[16 + qq * 4 + 0] + s2 * W[32 + qq * 4 + 0];
                float m1 = s0 * W[qq * 4 + 1] + s1 * W[16 + qq * 4 + 1] + s2 * W[32 + qq * 4 + 1];
                float m2 = s0 * W[qq * 4 + 2] + s1 * W[16 + qq * 4 + 2] + s2 * W[32 + qq * 4 + 2];
                float m3 = s0 * W[qq * 4 + 3] + s1 * W[16 + qq * 4 + 3] + s2 * W[32 + qq * 4 + 3];
                asm volatile("red.global.add.v4.f32 [%0], {%1, %2, %3, %4};"
                    :: "l"(op + qq * 4), "f"(m0), "f"(m1), "f"(m2), "f"(m3)
                    : "memory");
            }
        }
    }
}

// Node epilogue for layer 1 + layer-2 GEMV:
//   h1 = relu(dinv*agg1 + dinv^2*h_self + b1), z = h1 . W2
// where h_self = x @ W1, recomputed from the packed x.
__global__ void k_node_b(const float* __restrict__ W1,
                         const float* __restrict__ b1,
                         const float* __restrict__ W2) {
    float W[48];
#pragma unroll
    for (int j = 0; j < 48; ++j) W[j] = __ldg(W1 + j);
    int n = blockIdx.x * blockDim.x + threadIdx.x;
    if (n >= NN) return;
    float4 p = g_xp[n];
    float d = p.w;
    float d2 = d * d;
    const float4* ap = reinterpret_cast<const float4*>(g_agg1 + (size_t)n * F);
    float acc = 0.0f;
#pragma unroll
    for (int qq = 0; qq < 4; ++qq) {
        float4 a = ap[qq];
        float av[4] = {a.x, a.y, a.z, a.w};
#pragma unroll
        for (int j = 0; j < 4; ++j) {
            int k = qq * 4 + j;
            float hs = p.x * W[k] + p.y * W[16 + k] + p.z * W[32 + k];
            float h1 = av[j] * d + hs * d2 + __ldg(b1 + k);
            h1 = fmaxf(h1, 0.0f);
            acc += h1 * __ldg(W2 + k);
        }
    }
    g_z[n] = acc;
    g_zn[n] = acc * d;
}

// Layer-2 edge aggregation: 4 edges/thread; single 4B gather + scalar RED each.
__global__ void k_edge2(const int* __restrict__ row, const int* __restrict__ col) {
    int i = blockIdx.x * blockDim.x + threadIdx.x;
    int e = i * 4;
    if (e + 3 < NE) {
        int4 r4 = *reinterpret_cast<const int4*>(row + e);
        int4 c4 = *reinterpret_cast<const int4*>(col + e);
        float v0 = __ldg(&g_zn[r4.x]);
        float v1 = __ldg(&g_zn[r4.y]);
        float v2 = __ldg(&g_zn[r4.z]);
        float v3 = __ldg(&g_zn[r4.w]);
        atomicAdd(&g_agg2[c4.x], v0);
        atomicAdd(&g_agg2[c4.y], v1);
        atomicAdd(&g_agg2[c4.z], v2);
        atomicAdd(&g_agg2[c4.w], v3);
    } else {
        for (; e < NE; ++e)
            atomicAdd(&g_agg2[col[e]], __ldg(&g_zn[row[e]]));
    }
}

// Epilogue: apply target-side dinv, self-loop, bias.
__global__ void k_out(float* __restrict__ out, const float* __restrict__ b2) {
    int n = blockIdx.x * blockDim.x + threadIdx.x;
    if (n >= NN) return;
    float d = g_dinv[n];
    out[n] = g_agg2[n] * d + g_z[n] * d * d + __ldg(b2);
}

// ---------------------------------------------------------------------------
extern "C" void kernel_launch(void* const* d_in, const int* in_sizes, int n_in,
                              void* d_out, int out_size) {
    const float* x   = (const float*)d_in[0];
    const int*   ei  = (const int*)d_in[1];     // [2, NE] flattened
    const float* W1  = (const float*)d_in[2];
    const float* b1  = (const float*)d_in[3];
    const float* W2  = (const float*)d_in[4];
    const float* b2  = (const float*)d_in[5];
    float* out = (float*)d_out;

    const int* row = ei;        // edge_index[0] = sources
    const int* col = ei + NE;   // edge_index[1] = targets

    const int T = 256;
    k_zero<<<1184, T>>>();
    k_deg<<<(NE / 4 + T - 1) / T, T>>>(col);
    k_prep<<<(NN + T - 1) / T, T>>>(x);
    k_edge1<<<1184, T, 0>>>(row, col, W1);       // grid-stride, ~3.4 quads/thread
    k_node_b<<<(NN + T - 1) / T, T>>>(W1, b1, W2);
    k_edge2<<<(NE / 4 + T - 1) / T, T>>>(row, col);
    k_out<<<(NN + T - 1) / T, T>>>(out, b2);
}

// round 8
// speedup vs baseline: 1.6341x; 1.6341x over previous
#include <cuda_runtime.h>
#include <cuda_bf16.h>

// GCN 2-layer: x[500000,3], edge_index[2,4000000] (int32), W1[3,16], b1[16],
// W2[16,1], b2[1] -> out[500000,1] float32.
//
// Algebraic restructure v2:
//  - target-side dinv_c factored out of edge sums (applied at node epilogue)
//  - W1 pushed past the linear scatter-add: edges aggregate the RAW 3-vector
//    s[c] = sum_r dinv_r * x_r  (ONE red.global.add.v4.f32 per edge),
//    then out1 = ((dinv_c*(s[c] + dinv_c*x_c)) @ W1) + b1 per node.
//  - layer 2 aggregates the scalar zn = dinv*z per edge.

constexpr int NN = 500000;
constexpr int NE = 4000000;

// Scratch (device globals: allocation-free per harness rules)
__device__ float4 g_xp[NN];    // {d*x0, d*x1, d*x2, d} per node
__device__ float4 g_agg1[NN];  // layer-1 edge agg of 3-vectors (w unused)
__device__ float  g_dinv[NN];  // deg^{-1/2}
__device__ float  g_zn[NN];    // dinv * z  (layer-2 linear output, pre-scaled)
__device__ float  g_agg2[NN];  // layer-2 edge agg
__device__ int    g_deg[NN];   // incoming-edge count

// ---------------------------------------------------------------------------
__global__ void k_zero() {
    int tid = blockIdx.x * blockDim.x + threadIdx.x;
    int stride = gridDim.x * blockDim.x;
    for (int j = tid; j < NN; j += stride) {
        g_agg1[j] = make_float4(0.f, 0.f, 0.f, 0.f);
        g_agg2[j] = 0.0f;
        g_deg[j] = 0;
    }
}

// Degree of target nodes. 4 edges per thread via int4 load; g_deg (2MB) is
// L2-resident.
__global__ void k_deg(const int* __restrict__ col) {
    int i = blockIdx.x * blockDim.x + threadIdx.x;
    int e = i * 4;
    if (e >= NE) return;
    int4 c4 = *reinterpret_cast<const int4*>(col + e);
    atomicAdd(&g_deg[c4.x], 1);
    atomicAdd(&g_deg[c4.y], 1);
    atomicAdd(&g_deg[c4.z], 1);
    atomicAdd(&g_deg[c4.w], 1);
}

// Pack pre-scaled {d*x, d} per node.
__global__ void k_prep(const float* __restrict__ x) {
    int n = blockIdx.x * blockDim.x + threadIdx.x;
    if (n >= NN) return;
    float d = rsqrtf((float)(g_deg[n] + 1));  // + self-loop
    g_dinv[n] = d;
    float4 p;
    p.x = d * x[(size_t)n * 3 + 0];
    p.y = d * x[(size_t)n * 3 + 1];
    p.z = d * x[(size_t)n * 3 + 2];
    p.w = d;
    g_xp[n] = p;
}

// Dominant kernel: 4 edges per thread. Per edge: one 16B gather + one RED.v4.
__global__ void k_edge1(const int* __restrict__ row, const int* __restrict__ col) {
    int i = blockIdx.x * blockDim.x + threadIdx.x;
    int e = i * 4;
    if (e >= NE) return;
    int4 r4 = *reinterpret_cast<const int4*>(row + e);
    int4 c4 = *reinterpret_cast<const int4*>(col + e);
    // Front-batch the 4 independent gathers (MLP=4 per thread).
    float4 p0 = __ldg(&g_xp[r4.x]);
    float4 p1 = __ldg(&g_xp[r4.y]);
    float4 p2 = __ldg(&g_xp[r4.z]);
    float4 p3 = __ldg(&g_xp[r4.w]);
    asm volatile("red.global.add.v4.f32 [%0], {%1, %2, %3, %4};"
        :: "l"(&g_agg1[c4.x]), "f"(p0.x), "f"(p0.y), "f"(p0.z), "f"(0.f) : "memory");
    asm volatile("red.global.add.v4.f32 [%0], {%1, %2, %3, %4};"
        :: "l"(&g_agg1[c4.y]), "f"(p1.x), "f"(p1.y), "f"(p1.z), "f"(0.f) : "memory");
    asm volatile("red.global.add.v4.f32 [%0], {%1, %2, %3, %4};"
        :: "l"(&g_agg1[c4.z]), "f"(p2.x), "f"(p2.y), "f"(p2.z), "f"(0.f) : "memory");
    asm volatile("red.global.add.v4.f32 [%0], {%1, %2, %3, %4};"
        :: "l"(&g_agg1[c4.w]), "f"(p3.x), "f"(p3.y), "f"(p3.z), "f"(0.f) : "memory");
}

// Node epilogue layer 1 + layer-2 GEMV:
//   t = d * (agg1 + xp.xyz)          (3-vector; xp pre-scaled by d)
//   h1 = relu(t @ W1 + b1)           (16-wide, in registers)
//   z  = h1 . W2 ;  zn = d * z
__global__ void k_node_b(const float* __restrict__ W1,
                         const float* __restrict__ b1,
                         const float* __restrict__ W2) {
    __shared__ float sW[48], sB1[16], sW2[16];
    if (threadIdx.x < 48) sW[threadIdx.x] = W1[threadIdx.x];
    if (threadIdx.x >= 64 && threadIdx.x < 80) sB1[threadIdx.x - 64] = b1[threadIdx.x - 64];
    if (threadIdx.x >= 96 && threadIdx.x < 112) sW2[threadIdx.x - 96] = W2[threadIdx.x - 96];
    __syncthreads();
    int n = blockIdx.x * blockDim.x + threadIdx.x;
    if (n >= NN) return;
    float4 a = g_agg1[n];
    float4 p = g_xp[n];
    float d = p.w;
    float t0 = d * (a.x + p.x);
    float t1 = d * (a.y + p.y);
    float t2 = d * (a.z + p.z);
    float acc = 0.0f;
#pragma unroll
    for (int k = 0; k < 16; ++k) {
        float h1 = t0 * sW[k] + t1 * sW[16 + k] + t2 * sW[32 + k] + sB1[k];
        h1 = fmaxf(h1, 0.0f);
        acc += h1 * sW2[k];
    }
    g_zn[n] = acc * d;
}

// Layer-2 edge aggregation: 4 edges/thread; 4B gather + scalar RED each.
__global__ void k_edge2(const int* __restrict__ row, const int* __restrict__ col) {
    int i = blockIdx.x * blockDim.x + threadIdx.x;
    int e = i * 4;
    if (e >= NE) return;
    int4 r4 = *reinterpret_cast<const int4*>(row + e);
    int4 c4 = *reinterpret_cast<const int4*>(col + e);
    float v0 = __ldg(&g_zn[r4.x]);
    float v1 = __ldg(&g_zn[r4.y]);
    float v2 = __ldg(&g_zn[r4.z]);
    float v3 = __ldg(&g_zn[r4.w]);
    atomicAdd(&g_agg2[c4.x], v0);
    atomicAdd(&g_agg2[c4.y], v1);
    atomicAdd(&g_agg2[c4.z], v2);
    atomicAdd(&g_agg2[c4.w], v3);
}

// Epilogue: out = d*(agg2 + zn) + b2   (zn = d*z, so d*zn = d^2*z self-loop)
__global__ void k_out(float* __restrict__ out, const float* __restrict__ b2) {
    int n = blockIdx.x * blockDim.x + threadIdx.x;
    if (n >= NN) return;
    float d = g_dinv[n];
    out[n] = d * (g_agg2[n] + g_zn[n]) + __ldg(b2);
}

// ---------------------------------------------------------------------------
extern "C" void kernel_launch(void* const* d_in, const int* in_sizes, int n_in,
                              void* d_out, int out_size) {
    const float* x   = (const float*)d_in[0];
    const int*   ei  = (const int*)d_in[1];     // [2, NE] flattened
    const float* W1  = (const float*)d_in[2];
    const float* b1  = (const float*)d_in[3];
    const float* W2  = (const float*)d_in[4];
    const float* b2  = (const float*)d_in[5];
    float* out = (float*)d_out;

    const int* row = ei;        // edge_index[0] = sources
    const int* col = ei + NE;   // edge_index[1] = targets

    const int T = 256;
    k_zero<<<592, T>>>();                          // grid-stride, ~3.3 iters/thread
    k_deg<<<(NE / 4 + T - 1) / T, T>>>(col);
    k_prep<<<(NN + T - 1) / T, T>>>(x);
    k_edge1<<<(NE / 4 + T - 1) / T, T>>>(row, col);
    k_node_b<<<(NN + T - 1) / T, T>>>(W1, b1, W2);
    k_edge2<<<(NE / 4 + T - 1) / T, T>>>(row, col);
    k_out<<<(NN + T - 1) / T, T>>>(out, b2);
}

// round 9
// speedup vs baseline: 1.6520x; 1.0109x over previous
#include <cuda_runtime.h>
#include <cuda_bf16.h>

// GCN 2-layer: x[500000,3], edge_index[2,4000000] (int32), W1[3,16], b1[16],
// W2[16,1], b2[1] -> out[500000,1] float32.
//
// Algebraic restructure v2 (measured 100.5us):
//  - target-side dinv_c factored out of edge sums (applied at node epilogue)
//  - W1 pushed past the linear scatter-add: edges aggregate the RAW 3-vector
//    s[c] = sum_r dinv_r * x_r  (ONE red.global.add.v4.f32 per edge)
//  - layer 2 aggregates scalar zn = dinv*z per edge, RED directly into d_out
//    (seeded with the self-loop term), k_out finishes in place.
// v3 deltas: agg1 zeroed in k_prep; g_agg2 eliminated; __ldcs on idx streams.

constexpr int NN = 500000;
constexpr int NE = 4000000;

// Scratch (device globals: allocation-free per harness rules)
__device__ float4 g_xp[NN];    // {d*x0, d*x1, d*x2, d} per node
__device__ float4 g_agg1[NN];  // layer-1 edge agg of 3-vectors (w unused)
__device__ float  g_dinv[NN];  // deg^{-1/2}
__device__ float  g_zn[NN];    // dinv * z  (layer-2 linear output, pre-scaled)
__device__ int    g_deg[NN];   // incoming-edge count

// ---------------------------------------------------------------------------
// Zero only g_deg (2MB). agg1 zeroing folded into k_prep; agg2 eliminated.
__global__ void k_zero() {
    int n = blockIdx.x * blockDim.x + threadIdx.x;
    if (n < NN) g_deg[n] = 0;
}

// Degree of target nodes. 4 edges per thread; idx loads streamed (evict-first).
__global__ void k_deg(const int* __restrict__ col) {
    int i = blockIdx.x * blockDim.x + threadIdx.x;
    int e = i * 4;
    if (e >= NE) return;
    int4 c4 = __ldcs(reinterpret_cast<const int4*>(col + e));
    atomicAdd(&g_deg[c4.x], 1);
    atomicAdd(&g_deg[c4.y], 1);
    atomicAdd(&g_deg[c4.z], 1);
    atomicAdd(&g_deg[c4.w], 1);
}

// Pack pre-scaled {d*x, d} per node; zero agg1 in the same pass.
__global__ void k_prep(const float* __restrict__ x) {
    int n = blockIdx.x * blockDim.x + threadIdx.x;
    if (n >= NN) return;
    float d = rsqrtf((float)(g_deg[n] + 1));  // + self-loop
    g_dinv[n] = d;
    float4 p;
    p.x = d * x[(size_t)n * 3 + 0];
    p.y = d * x[(size_t)n * 3 + 1];
    p.z = d * x[(size_t)n * 3 + 2];
    p.w = d;
    g_xp[n] = p;
    g_agg1[n] = make_float4(0.f, 0.f, 0.f, 0.f);
}

// Dominant kernel: 4 edges per thread. Per edge: one 16B gather + one RED.v4.
__global__ void k_edge1(const int* __restrict__ row, const int* __restrict__ col) {
    int i = blockIdx.x * blockDim.x + threadIdx.x;
    int e = i * 4;
    if (e >= NE) return;
    int4 r4 = __ldcs(reinterpret_cast<const int4*>(row + e));
    int4 c4 = __ldcs(reinterpret_cast<const int4*>(col + e));
    // Front-batch the 4 independent gathers (MLP=4 per thread).
    float4 p0 = __ldg(&g_xp[r4.x]);
    float4 p1 = __ldg(&g_xp[r4.y]);
    float4 p2 = __ldg(&g_xp[r4.z]);
    float4 p3 = __ldg(&g_xp[r4.w]);
    asm volatile("red.global.add.v4.f32 [%0], {%1, %2, %3, %4};"
        :: "l"(&g_agg1[c4.x]), "f"(p0.x), "f"(p0.y), "f"(p0.z), "f"(0.f) : "memory");
    asm volatile("red.global.add.v4.f32 [%0], {%1, %2, %3, %4};"
        :: "l"(&g_agg1[c4.y]), "f"(p1.x), "f"(p1.y), "f"(p1.z), "f"(0.f) : "memory");
    asm volatile("red.global.add.v4.f32 [%0], {%1, %2, %3, %4};"
        :: "l"(&g_agg1[c4.z]), "f"(p2.x), "f"(p2.y), "f"(p2.z), "f"(0.f) : "memory");
    asm volatile("red.global.add.v4.f32 [%0], {%1, %2, %3, %4};"
        :: "l"(&g_agg1[c4.w]), "f"(p3.x), "f"(p3.y), "f"(p3.z), "f"(0.f) : "memory");
}

// Node epilogue layer 1 + layer-2 GEMV:
//   t = d * (agg1 + xp.xyz); h1 = relu(t @ W1 + b1); z = h1 . W2; zn = d*z
// Also seeds d_out[n] = zn[n] (self-loop term) so edge2 can RED into d_out.
__global__ void k_node_b(const float* __restrict__ W1,
                         const float* __restrict__ b1,
                         const float* __restrict__ W2,
                         float* __restrict__ out) {
    __shared__ float sW[48], sB1[16], sW2[16];
    if (threadIdx.x < 48) sW[threadIdx.x] = W1[threadIdx.x];
    if (threadIdx.x >= 64 && threadIdx.x < 80) sB1[threadIdx.x - 64] = b1[threadIdx.x - 64];
    if (threadIdx.x >= 96 && threadIdx.x < 112) sW2[threadIdx.x - 96] = W2[threadIdx.x - 96];
    __syncthreads();
    int n = blockIdx.x * blockDim.x + threadIdx.x;
    if (n >= NN) return;
    float4 a = g_agg1[n];
    float4 p = g_xp[n];
    float d = p.w;
    float t0 = d * (a.x + p.x);
    float t1 = d * (a.y + p.y);
    float t2 = d * (a.z + p.z);
    float acc = 0.0f;
#pragma unroll
    for (int k = 0; k < 16; ++k) {
        float h1 = t0 * sW[k] + t1 * sW[16 + k] + t2 * sW[32 + k] + sB1[k];
        h1 = fmaxf(h1, 0.0f);
        acc += h1 * sW2[k];
    }
    float zn = acc * d;
    g_zn[n] = zn;
    out[n] = zn;   // seed: self-loop contribution (pre-scaled by final d in k_out)
}

// Layer-2 edge aggregation: 4 edges/thread; 4B gather + scalar RED into d_out.
__global__ void k_edge2(const int* __restrict__ row, const int* __restrict__ col,
                        float* __restrict__ out) {
    int i = blockIdx.x * blockDim.x + threadIdx.x;
    int e = i * 4;
    if (e >= NE) return;
    int4 r4 = __ldcs(reinterpret_cast<const int4*>(row + e));
    int4 c4 = __ldcs(reinterpret_cast<const int4*>(col + e));
    float v0 = __ldg(&g_zn[r4.x]);
    float v1 = __ldg(&g_zn[r4.y]);
    float v2 = __ldg(&g_zn[r4.z]);
    float v3 = __ldg(&g_zn[r4.w]);
    atomicAdd(&out[c4.x], v0);
    atomicAdd(&out[c4.y], v1);
    atomicAdd(&out[c4.z], v2);
    atomicAdd(&out[c4.w], v3);
}

// Epilogue, in place: out = d*out + b2   (out currently = agg2 + zn)
__global__ void k_out(float* __restrict__ out, const float* __restrict__ b2) {
    int n = blockIdx.x * blockDim.x + threadIdx.x;
    if (n >= NN) return;
    out[n] = g_dinv[n] * out[n] + __ldg(b2);
}

// ---------------------------------------------------------------------------
extern "C" void kernel_launch(void* const* d_in, const int* in_sizes, int n_in,
                              void* d_out, int out_size) {
    const float* x   = (const float*)d_in[0];
    const int*   ei  = (const int*)d_in[1];     // [2, NE] flattened
    const float* W1  = (const float*)d_in[2];
    const float* b1  = (const float*)d_in[3];
    const float* W2  = (const float*)d_in[4];
    const float* b2  = (const float*)d_in[5];
    float* out = (float*)d_out;

    const int* row = ei;        // edge_index[0] = sources
    const int* col = ei + NE;   // edge_index[1] = targets

    const int T = 256;
    k_zero<<<(NN + T - 1) / T, T>>>();
    k_deg<<<(NE / 4 + T - 1) / T, T>>>(col);
    k_prep<<<(NN + T - 1) / T, T>>>(x);
    k_edge1<<<(NE / 4 + T - 1) / T, T>>>(row, col);
    k_node_b<<<(NN + T - 1) / T, T>>>(W1, b1, W2, out);
    k_edge2<<<(NE / 4 + T - 1) / T, T>>>(row, col, out);
    k_out<<<(NN + T - 1) / T, T>>>(out, b2);
}